// round 15
// baseline (speedup 1.0000x reference)
#include <cuda_runtime.h>
#include <cuda_fp16.h>
#include <math.h>

#define NNODES 50000
#define NEDGES 800000
#define CH_SCAN 512
#define NB_SCAN ((NNODES + CH_SCAN - 1) / CH_SCAN)   // 98

// ---------------- scratch (static device globals; no allocations) ----------
__device__ __half g_z[2 * NNODES * 256];     // fp16 per-etype GEMM output
__device__ float g_h1[NNODES * 128];
__device__ float g_h2[NNODES * 64];
__device__ float g_el[2 * NNODES * 4];
__device__ float g_er[2 * NNODES * 4];
__device__ float g_colsum[256];
__device__ int   g_rp[2][NNODES + 1];
__device__ int   g_cse[2][NEDGES];
__device__ int   g_wp[2][NNODES];
__device__ int   g_bsum[2][128];

// ---------------- f32x2 packed-FMA helpers ----------------
__device__ __forceinline__ unsigned long long bcast2(float v) {
    unsigned long long r;
    asm("mov.b64 %0, {%1, %1};" : "=l"(r) : "f"(v));
    return r;
}
__device__ __forceinline__ void ffma2(unsigned long long& d,
                                      unsigned long long a, unsigned long long b) {
    asm("fma.rn.f32x2 %0, %1, %2, %0;" : "+l"(d) : "l"(a), "l"(b));
}
__device__ __forceinline__ float2 unpack2(unsigned long long v) {
    float2 f;
    asm("mov.b64 {%0, %1}, %2;" : "=f"(f.x), "=f"(f.y) : "l"(v));
    return f;
}

__device__ __forceinline__ float lrelu(float v) {
    return (v > 0.0f) ? v : 0.2f * v;
}
__device__ __forceinline__ float2 h2f(const __half2 h) { return __half22float2(h); }

// ---------------- init: zero CSR counters AND colsum in one launch ----------
__global__ void zero_init(int* __restrict__ rpb, float* __restrict__ csum, int n) {
    int i = blockIdx.x * blockDim.x + threadIdx.x;
    if (i < n) rpb[i] = 0;
    if (i < 256) csum[i] = 0.0f;
}

// ---------------- CSR build pieces ----------------
__global__ void scan_local(int* __restrict__ rpb, int* __restrict__ bsumb) {
    __shared__ int s[CH_SCAN];
    int* rp = rpb + blockIdx.y * (NNODES + 1);
    int* bsum = bsumb + blockIdx.y * 128;
    int tid = threadIdx.x;
    int i = blockIdx.x * CH_SCAN + tid;
    int v = (i < NNODES) ? rp[i] : 0;
    s[tid] = v;
    __syncthreads();
    for (int off = 1; off < CH_SCAN; off <<= 1) {
        int t = (tid >= off) ? s[tid - off] : 0;
        __syncthreads();
        s[tid] += t;
        __syncthreads();
    }
    if (i < NNODES) rp[i] = s[tid] - v;
    if (tid == CH_SCAN - 1) bsum[blockIdx.x] = s[tid];
}

__global__ void scan_add_wp(int* __restrict__ rpb, const int* __restrict__ bsumb,
                            int* __restrict__ wpb) {
    __shared__ int sb[128];
    int tid = threadIdx.x;
    if (tid < 128) {
        int v = (tid < NB_SCAN) ? bsumb[blockIdx.y * 128 + tid] : 0;
        sb[tid] = v;
    }
    __syncthreads();
    for (int off = 1; off < 128; off <<= 1) {
        int t = (tid < 128 && tid >= off) ? sb[tid - off] : 0;
        __syncthreads();
        if (tid < 128) sb[tid] += t;
        __syncthreads();
    }
    int i = blockIdx.x * blockDim.x + tid;
    int* rp = rpb + blockIdx.y * (NNODES + 1);
    int* wp = wpb + blockIdx.y * NNODES;
    if (i < NNODES) {
        int c = i / CH_SCAN;
        int pre = (c == 0) ? 0 : sb[c - 1];
        int v = rp[i] + pre;
        rp[i] = v;
        wp[i] = v;
    }
    if (i == 0) rp[NNODES] = NEDGES;
}

__global__ void fill_k(const int* __restrict__ s0, const int* __restrict__ s1,
                       const int* __restrict__ d0, const int* __restrict__ d1,
                       int* __restrict__ wpb, int* __restrict__ csb) {
    int e = blockIdx.x * blockDim.x + threadIdx.x;
    if (e >= NEDGES) return;
    const int* src = blockIdx.y ? s1 : s0;
    const int* dst = blockIdx.y ? d1 : d0;
    int* wp = wpb + blockIdx.y * NNODES;
    int* cs = csb + blockIdx.y * NEDGES;
    int p = atomicAdd(&wp[dst[e]], 1);
    cs[p] = src[e];
}

// ---------------- GEMM body: double-buffered, f32x2 FMA ----------------
// H==4: z stored head-interleaved (zm[row][lane*8] = {headA quad, headB quad})
template <int K, int HF, int H>
__device__ __forceinline__ void
gemm_body(int bx, int by,
          const float* __restrict__ X, const float* __restrict__ Wb,
          const float* __restrict__ alb, const float* __restrict__ arb,
          __half* __restrict__ Zb, float* __restrict__ elb, float* __restrict__ erb) {
    constexpr int TN = 8, TM = 8, BK = 16;
    constexpr int TX = HF / TN;
    constexpr int TY = 256 / TX;
    constexpr int BM = TM * TY;
    constexpr int BMP = BM + 4;
    constexpr int RW = TX / H;
    constexpr int NT = K / BK;
    constexpr int NX = (BM * BK / 4) / 256;
    constexpr int NW = (BK * HF / 4) / 256;

    __shared__ float xs[2][BK][BMP];
    __shared__ float ws[2][BK][HF];

    const float* W  = Wb  + by * K * HF;
    const float* al = alb + by * HF;
    const float* ar = arb + by * HF;
    __half* Z = Zb  + by * (NNODES * 256);
    float* el = elb + by * (NNODES * 4);
    float* er = erb + by * (NNODES * 4);

    int tid = threadIdx.x;
    int tx = tid % TX;
    int ty = tid / TX;
    int r0 = bx * BM;

    float4 xr[NX], wr[NW];

    auto loadt = [&](int kb) {
#pragma unroll
        for (int it = 0; it < NX; it++) {
            int lin = (tid + it * 256) * 4;
            int r = lin / BK, c = lin % BK;
            int gr = r0 + r;
            xr[it] = (gr < NNODES) ? *(const float4*)&X[gr * K + kb + c]
                                   : make_float4(0.f, 0.f, 0.f, 0.f);
        }
#pragma unroll
        for (int it = 0; it < NW; it++) {
            int lin = (tid + it * 256) * 4;
            int r = lin / HF, c = lin % HF;
            wr[it] = *(const float4*)&W[(kb + r) * HF + c];
        }
    };
    auto storet = [&](int buf) {
#pragma unroll
        for (int it = 0; it < NX; it++) {
            int lin = (tid + it * 256) * 4;
            int r = lin / BK, c = lin % BK;
            xs[buf][c][r] = xr[it].x;
            xs[buf][c + 1][r] = xr[it].y;
            xs[buf][c + 2][r] = xr[it].z;
            xs[buf][c + 3][r] = xr[it].w;
        }
#pragma unroll
        for (int it = 0; it < NW; it++) {
            int lin = (tid + it * 256) * 4;
            int r = lin / HF, c = lin % HF;
            *(float4*)&ws[buf][r][c] = wr[it];
        }
    };

    unsigned long long acc2[TM][TN / 2];
#pragma unroll
    for (int i = 0; i < TM; i++)
#pragma unroll
        for (int j = 0; j < TN / 2; j++) acc2[i][j] = 0ull;

    loadt(0);
    storet(0);
#pragma unroll
    for (int t = 0; t < NT; t++) {
        __syncthreads();
        if (t + 1 < NT) loadt((t + 1) * BK);
        int buf = t & 1;
#pragma unroll
        for (int kk = 0; kk < BK; kk++) {
            float4 a0 = *(const float4*)&xs[buf][kk][ty * 8];
            float4 a1 = *(const float4*)&xs[buf][kk][ty * 8 + 4];
            const unsigned long long* wp64 =
                (const unsigned long long*)&ws[buf][kk][tx * 8];
            unsigned long long bp0 = wp64[0], bp1 = wp64[1],
                               bp2 = wp64[2], bp3 = wp64[3];
            unsigned long long ap[TM] = {
                bcast2(a0.x), bcast2(a0.y), bcast2(a0.z), bcast2(a0.w),
                bcast2(a1.x), bcast2(a1.y), bcast2(a1.z), bcast2(a1.w)};
#pragma unroll
            for (int i = 0; i < TM; i++) {
                ffma2(acc2[i][0], ap[i], bp0);
                ffma2(acc2[i][1], ap[i], bp1);
                ffma2(acc2[i][2], ap[i], bp2);
                ffma2(acc2[i][3], ap[i], bp3);
            }
        }
        if (t + 1 < NT) storet((t + 1) & 1);
    }

    int cbase = tx * TN;
#pragma unroll
    for (int i = 0; i < TM; i++) {
        int row = r0 + ty * TM + i;
        float2 u0 = unpack2(acc2[i][0]);
        float2 u1 = unpack2(acc2[i][1]);
        float2 u2 = unpack2(acc2[i][2]);
        float2 u3 = unpack2(acc2[i][3]);
        float av[TN] = {u0.x, u0.y, u1.x, u1.y, u2.x, u2.y, u3.x, u3.y};
        float pl = 0.0f, pr = 0.0f;
#pragma unroll
        for (int j = 0; j < TN; j++) {
            pl += av[j] * al[cbase + j];
            pr += av[j] * ar[cbase + j];
        }
#pragma unroll
        for (int o = RW / 2; o > 0; o >>= 1) {
            pl += __shfl_xor_sync(0xffffffffu, pl, o);
            pr += __shfl_xor_sync(0xffffffffu, pr, o);
        }
        if (row < NNODES) {
            if constexpr (H == 4) {
                uint2 v0, v1;
                ((__half2*)&v0)[0] = __floats2half2_rn(av[0], av[1]);
                ((__half2*)&v0)[1] = __floats2half2_rn(av[2], av[3]);
                ((__half2*)&v1)[0] = __floats2half2_rn(av[4], av[5]);
                ((__half2*)&v1)[1] = __floats2half2_rn(av[6], av[7]);
                int cm = cbase & 127;
                int hoff = (cbase >= 128) ? 4 : 0;
                int nb0 = (cm >> 2) * 8 + hoff;
                *(uint2*)&Z[row * 256 + nb0] = v0;
                *(uint2*)&Z[row * 256 + nb0 + 8] = v1;
            } else {
                uint4 pack;
                __half2* ph = (__half2*)&pack;
                ph[0] = __floats2half2_rn(av[0], av[1]);
                ph[1] = __floats2half2_rn(av[2], av[3]);
                ph[2] = __floats2half2_rn(av[4], av[5]);
                ph[3] = __floats2half2_rn(av[6], av[7]);
                *(uint4*)&Z[row * HF + cbase] = pack;
            }
            if (tx % RW == 0) {
                int h = tx / RW;
                el[row * H + h] = pl;
                er[row * H + h] = pr;
            }
        }
    }
}

template <int K, int HF, int H>
__global__ void __launch_bounds__(256)
gemm_att(const float* __restrict__ X, const float* __restrict__ Wb,
         const float* __restrict__ alb, const float* __restrict__ arb,
         __half* __restrict__ Zb, float* __restrict__ elb, float* __restrict__ erb) {
    gemm_body<K, HF, H>(blockIdx.x, blockIdx.y, X, Wb, alb, arb, Zb, elb, erb);
}

__global__ void __launch_bounds__(256)
gemm1_count(const float* __restrict__ X, const float* __restrict__ Wb,
            const float* __restrict__ alb, const float* __restrict__ arb,
            __half* __restrict__ Zb, float* __restrict__ elb, float* __restrict__ erb,
            const int* __restrict__ d0, const int* __restrict__ d1,
            int* __restrict__ rpb, int gemmX, int countBlocks) {
    if ((int)blockIdx.x < gemmX) {
        gemm_body<128, 128, 1>(blockIdx.x, blockIdx.y, X, Wb, alb, arb, Zb, elb, erb);
    } else {
        int cb = blockIdx.x - gemmX;
        const int* dst = blockIdx.y ? d1 : d0;
        int* cnt = rpb + blockIdx.y * (NNODES + 1);
        for (int e = cb * 256 + threadIdx.x; e < NEDGES; e += countBlocks * 256)
            atomicAdd(&cnt[dst[e]], 1);
    }
}

// ---------------- single-pass CSR softmax + gather aggregation ----------------
// Lane-parallel edge metadata + deep gather pipelines (UNR 16/16/8).
template <int HF, int H>
__global__ void __launch_bounds__(256)
gat_agg(const int* __restrict__ rp0, const int* __restrict__ cs0,
        const int* __restrict__ rp1, const int* __restrict__ cs1,
        const __half* __restrict__ z0, const __half* __restrict__ z1,
        const float* __restrict__ el0, const float* __restrict__ er0,
        const float* __restrict__ el1, const float* __restrict__ er1,
        const float* __restrict__ bia,
        const float* __restrict__ fc,
        float* __restrict__ out,
        float* __restrict__ colsum) {
    constexpr int VEC = HF / 32;
    __shared__ float scp[256];
    if (HF == 256) {
        scp[threadIdx.x] = 0.0f;
        __syncthreads();
    }
    int w = (blockIdx.x * blockDim.x + threadIdx.x) >> 5;
    int lane = threadIdx.x & 31;

    float c0 = 0.5f, c1 = 0.5f;
    if (fc) { c0 = 0.5f * (fc[0] + fc[2]); c1 = 0.5f * (fc[1] + fc[3]); }

    float acc[VEC];
#pragma unroll
    for (int i = 0; i < VEC; i++) acc[i] = 0.0f;

    if (w < NNODES) {
#pragma unroll
        for (int et = 0; et < 2; et++) {
            const int* rp = et ? rp1 : rp0;
            const int* cs = et ? cs1 : cs0;
            const __half* z = et ? z1 : z0;
            const float* el = et ? el1 : el0;
            const float* er = et ? er1 : er0;
            float ce = et ? c1 : c0;

            int beg = rp[w];
            int end = rp[w + 1];
            if (beg == end) continue;

            float accE[VEC];
#pragma unroll
            for (int i = 0; i < VEC; i++) accE[i] = 0.0f;

            if constexpr (H == 1) {
                constexpr int UNR = 16;
                float ern = er[w];
                float den = 0.0f;
                int i = beg;
                for (; i + UNR <= end; i += UNR) {
                    int myS = 0;
                    float myW = 0.0f;
                    if (lane < UNR) {
                        myS = cs[i + lane];
                        myW = __expf(lrelu(el[myS] + ern));
                    }
                    int s[UNR];
                    float wt[UNR];
#pragma unroll
                    for (int u = 0; u < UNR; u++) {
                        s[u] = __shfl_sync(0xffffffffu, myS, u);
                        wt[u] = __shfl_sync(0xffffffffu, myW, u);
                    }
                    if constexpr (HF == 128) {
                        uint2 p[UNR];
#pragma unroll
                        for (int u = 0; u < UNR; u++)
                            p[u] = *(const uint2*)&z[s[u] * 128 + lane * 4];
#pragma unroll
                        for (int u = 0; u < UNR; u++) {
                            float2 f0 = h2f(((const __half2*)&p[u])[0]);
                            float2 f1 = h2f(((const __half2*)&p[u])[1]);
                            accE[0] += wt[u] * f0.x;
                            accE[1] += wt[u] * f0.y;
                            accE[2] += wt[u] * f1.x;
                            accE[3] += wt[u] * f1.y;
                            den += wt[u];
                        }
                    } else {  // HF == 64
                        unsigned p[UNR];
#pragma unroll
                        for (int u = 0; u < UNR; u++)
                            p[u] = *(const unsigned*)&z[s[u] * 64 + lane * 2];
#pragma unroll
                        for (int u = 0; u < UNR; u++) {
                            float2 f0 = h2f(*(const __half2*)&p[u]);
                            accE[0] += wt[u] * f0.x;
                            accE[1] += wt[u] * f0.y;
                            den += wt[u];
                        }
                    }
                }
                for (; i < end; i++) {
                    int s = cs[i];
                    float wt = __expf(lrelu(el[s] + ern));
                    den += wt;
                    if constexpr (HF == 128) {
                        uint2 p = *(const uint2*)&z[s * 128 + lane * 4];
                        float2 f0 = h2f(((const __half2*)&p)[0]);
                        float2 f1 = h2f(((const __half2*)&p)[1]);
                        accE[0] += wt * f0.x; accE[1] += wt * f0.y;
                        accE[2] += wt * f1.x; accE[3] += wt * f1.y;
                    } else {
                        float2 f0 = h2f(*(const __half2*)&z[s * 64 + lane * 2]);
                        accE[0] += wt * f0.x; accE[1] += wt * f0.y;
                    }
                }
                float sc1 = ce / fmaxf(den, 1e-30f);
#pragma unroll
                for (int j = 0; j < VEC; j++) acc[j] += accE[j] * sc1;
            } else {  // H == 4, HF == 256, z head-interleaved
                constexpr int UNR = 8;
                int hsel = lane >> 4;              // 0: heads (0,2); 1: heads (1,3)
                float4 er4 = *(const float4*)&er[w * 4];
                float den0 = 0.0f, den1 = 0.0f;
                int i = beg;
                for (; i + UNR <= end; i += UNR) {
                    int myS = 0;
                    float4 myW = make_float4(0.f, 0.f, 0.f, 0.f);
                    if (lane < UNR) {
                        myS = cs[i + lane];
                        float4 e4 = *(const float4*)&el[myS * 4];
                        myW.x = __expf(lrelu(e4.x + er4.x));
                        myW.y = __expf(lrelu(e4.y + er4.y));
                        myW.z = __expf(lrelu(e4.z + er4.z));
                        myW.w = __expf(lrelu(e4.w + er4.w));
                    }
                    int s[UNR];
                    float w0[UNR], w1[UNR];
#pragma unroll
                    for (int u = 0; u < UNR; u++) {
                        s[u] = __shfl_sync(0xffffffffu, myS, u);
                        float a = __shfl_sync(0xffffffffu, myW.x, u);
                        float b = __shfl_sync(0xffffffffu, myW.y, u);
                        float c = __shfl_sync(0xffffffffu, myW.z, u);
                        float d = __shfl_sync(0xffffffffu, myW.w, u);
                        w0[u] = hsel ? b : a;
                        w1[u] = hsel ? d : c;
                    }
                    uint4 p[UNR];
#pragma unroll
                    for (int u = 0; u < UNR; u++)
                        p[u] = *(const uint4*)&z[s[u] * 256 + lane * 8];
#pragma unroll
                    for (int u = 0; u < UNR; u++) {
                        float2 f00 = h2f(((const __half2*)&p[u])[0]);
                        float2 f01 = h2f(((const __half2*)&p[u])[1]);
                        float2 f10 = h2f(((const __half2*)&p[u])[2]);
                        float2 f11 = h2f(((const __half2*)&p[u])[3]);
                        accE[0] += w0[u] * f00.x; accE[1] += w0[u] * f00.y;
                        accE[2] += w0[u] * f01.x; accE[3] += w0[u] * f01.y;
                        accE[4] += w1[u] * f10.x; accE[5] += w1[u] * f10.y;
                        accE[6] += w1[u] * f11.x; accE[7] += w1[u] * f11.y;
                        den0 += w0[u];
                        den1 += w1[u];
                    }
                }
                for (; i < end; i++) {
                    int s = cs[i];
                    int h0 = hsel, h1 = 2 + hsel;
                    float ern0 = hsel ? er4.y : er4.x;
                    float ern1 = hsel ? er4.w : er4.z;
                    float w0 = __expf(lrelu(el[s * 4 + h0] + ern0));
                    float w1 = __expf(lrelu(el[s * 4 + h1] + ern1));
                    uint4 p = *(const uint4*)&z[s * 256 + lane * 8];
                    float2 f00 = h2f(((const __half2*)&p)[0]);
                    float2 f01 = h2f(((const __half2*)&p)[1]);
                    float2 f10 = h2f(((const __half2*)&p)[2]);
                    float2 f11 = h2f(((const __half2*)&p)[3]);
                    accE[0] += w0 * f00.x; accE[1] += w0 * f00.y;
                    accE[2] += w0 * f01.x; accE[3] += w0 * f01.y;
                    accE[4] += w1 * f10.x; accE[5] += w1 * f10.y;
                    accE[6] += w1 * f11.x; accE[7] += w1 * f11.y;
                    den0 += w0;
                    den1 += w1;
                }
                float s0 = ce / fmaxf(den0, 1e-30f);
                float s1 = ce / fmaxf(den1, 1e-30f);
#pragma unroll
                for (int j = 0; j < 4; j++) acc[j] += accE[j] * s0;
#pragma unroll
                for (int j = 4; j < 8; j++) acc[j] += accE[j] * s1;
            }
        }

        // write output with combined bias
        if constexpr (HF == 64) {
            int f = lane * 2;
            float2 o;
            o.x = acc[0] + c0 * bia[f] + c1 * bia[64 + f];
            o.y = acc[1] + c0 * bia[f + 1] + c1 * bia[64 + f + 1];
            *(float2*)&out[w * 64 + f] = o;
        } else if constexpr (HF == 128) {
            int f = lane * 4;
            float4 o;
            o.x = acc[0] + c0 * bia[f + 0] + c1 * bia[128 + f + 0];
            o.y = acc[1] + c0 * bia[f + 1] + c1 * bia[128 + f + 1];
            o.z = acc[2] + c0 * bia[f + 2] + c1 * bia[128 + f + 2];
            o.w = acc[3] + c0 * bia[f + 3] + c1 * bia[128 + f + 3];
            *(float4*)&out[w * 128 + f] = o;
        } else {
            int f = lane * 4;
            float4 o0, o1;
            o0.x = acc[0] + 0.5f * (bia[f + 0] + bia[256 + f + 0]);
            o0.y = acc[1] + 0.5f * (bia[f + 1] + bia[256 + f + 1]);
            o0.z = acc[2] + 0.5f * (bia[f + 2] + bia[256 + f + 2]);
            o0.w = acc[3] + 0.5f * (bia[f + 3] + bia[256 + f + 3]);
            o1.x = acc[4] + 0.5f * (bia[128 + f + 0] + bia[256 + 128 + f + 0]);
            o1.y = acc[5] + 0.5f * (bia[128 + f + 1] + bia[256 + 128 + f + 1]);
            o1.z = acc[6] + 0.5f * (bia[128 + f + 2] + bia[256 + 128 + f + 2]);
            o1.w = acc[7] + 0.5f * (bia[128 + f + 3] + bia[256 + 128 + f + 3]);
            *(float4*)&out[w * 256 + f] = o0;
            *(float4*)&out[w * 256 + 128 + f] = o1;
            atomicAdd(&scp[f + 0], o0.x);
            atomicAdd(&scp[f + 1], o0.y);
            atomicAdd(&scp[f + 2], o0.z);
            atomicAdd(&scp[f + 3], o0.w);
            atomicAdd(&scp[128 + f + 0], o1.x);
            atomicAdd(&scp[128 + f + 1], o1.y);
            atomicAdd(&scp[128 + f + 2], o1.z);
            atomicAdd(&scp[128 + f + 3], o1.w);
        }
    }

    if (HF == 256) {
        __syncthreads();
        atomicAdd(&colsum[threadIdx.x], scp[threadIdx.x]);
    }
}

// ---------------- final centering (float4) ----------------
__global__ void center_kernel(float* __restrict__ out, const float* __restrict__ cs) {
    int i = blockIdx.x * blockDim.x + threadIdx.x;     // quad index
    if (i < NNODES * 64) {
        int f = (i & 63) * 4;
        float4 v = *(float4*)&out[i * 4];
        v.x -= cs[f + 0] * (1.0f / NNODES);
        v.y -= cs[f + 1] * (1.0f / NNODES);
        v.z -= cs[f + 2] * (1.0f / NNODES);
        v.w -= cs[f + 3] * (1.0f / NNODES);
        *(float4*)&out[i * 4] = v;
    }
}

// ---------------- orchestration ----------------
extern "C" void kernel_launch(void* const* d_in, const int* in_sizes, int n_in,
                              void* d_out, int out_size) {
    const float* x   = (const float*)d_in[0];
    const int* src0 = (const int*)d_in[1];
    const int* dst0 = (const int*)d_in[2];
    const int* src1 = (const int*)d_in[3];
    const int* dst1 = (const int*)d_in[4];
    const float* W1  = (const float*)d_in[5];
    const float* al1 = (const float*)d_in[6];
    const float* ar1 = (const float*)d_in[7];
    const float* b1  = (const float*)d_in[8];
    const float* W2  = (const float*)d_in[9];
    const float* al2 = (const float*)d_in[10];
    const float* ar2 = (const float*)d_in[11];
    const float* b2  = (const float*)d_in[12];
    const float* Wm  = (const float*)d_in[13];
    const float* alm = (const float*)d_in[14];
    const float* arm = (const float*)d_in[15];
    const float* bm  = (const float*)d_in[16];
    const float* fc  = (const float*)d_in[17];
    float* out = (float*)d_out;

    __half* zb;
    float *h1, *h2, *elb, *erb, *csum;
    int *rpb, *cseb, *wpb, *bsumb;
    cudaGetSymbolAddress((void**)&zb,    g_z);
    cudaGetSymbolAddress((void**)&h1,    g_h1);
    cudaGetSymbolAddress((void**)&h2,    g_h2);
    cudaGetSymbolAddress((void**)&elb,   g_el);
    cudaGetSymbolAddress((void**)&erb,   g_er);
    cudaGetSymbolAddress((void**)&csum,  g_colsum);
    cudaGetSymbolAddress((void**)&rpb,   g_rp);
    cudaGetSymbolAddress((void**)&cseb,  g_cse);
    cudaGetSymbolAddress((void**)&wpb,   g_wp);
    cudaGetSymbolAddress((void**)&bsumb, g_bsum);

    int* rp[2]  = {rpb, rpb + (NNODES + 1)};
    int* cse[2] = {cseb, cseb + NEDGES};
    __half* z[2] = {zb, zb + NNODES * 256};
    float* el[2] = {elb, elb + NNODES * 4};
    float* er[2] = {erb, erb + NNODES * 4};

    const int EG = (NEDGES + 255) / 256;
    const int AGG_BLOCKS = (NNODES * 32 + 255) / 256;

    // ---------------- zero counters + colsum, then fused GEMM1 + count -----
    zero_init<<<(2 * (NNODES + 1) + 255) / 256, 256>>>(rpb, csum, 2 * (NNODES + 1));

    const int GEMM1_X = (NNODES + 127) / 128;
    const int COUNT_B = 256;
    gemm1_count<<<dim3(GEMM1_X + COUNT_B, 2), 256>>>(
        x, W1, al1, ar1, zb, elb, erb, dst0, dst1, rpb, GEMM1_X, COUNT_B);

    // ---------------- finish CSR build ----------------
    scan_local<<<dim3(NB_SCAN, 2), CH_SCAN>>>(rpb, bsumb);
    scan_add_wp<<<dim3((NNODES + 255) / 256, 2), 256>>>(rpb, bsumb, wpb);
    fill_k<<<dim3(EG, 2), 256>>>(src0, src1, dst0, dst1, wpb, cseb);

    // ---------------- layer 1 aggregation ----------------
    gat_agg<128, 1><<<AGG_BLOCKS, 256>>>(
        rp[0], cse[0], rp[1], cse[1], z[0], z[1],
        el[0], er[0], el[1], er[1], b1, nullptr, h1, nullptr);

    // ---------------- layer 2 ----------------
    gemm_att<128, 64, 1><<<dim3((NNODES + 255) / 256, 2), 256>>>(
        h1, W2, al2, ar2, zb, elb, erb);
    gat_agg<64, 1><<<AGG_BLOCKS, 256>>>(
        rp[0], cse[0], rp[1], cse[1], z[0], z[1],
        el[0], er[0], el[1], er[1], b2, fc, h2, nullptr);

    // ---------------- layer MH ----------------
    gemm_att<64, 256, 4><<<dim3((NNODES + 63) / 64, 2), 256>>>(
        h2, Wm, alm, arm, zb, elb, erb);
    gat_agg<256, 4><<<AGG_BLOCKS, 256>>>(
        rp[0], cse[0], rp[1], cse[1], z[0], z[1],
        el[0], er[0], el[1], er[1], bm, nullptr, out, csum);

    // ---------------- final per-column mean centering -------------------
    center_kernel<<<(NNODES * 64 + 255) / 256, 256>>>(out, csum);
}

// round 16
// speedup vs baseline: 1.0290x; 1.0290x over previous
#include <cuda_runtime.h>
#include <cuda_fp16.h>
#include <math.h>

#define NNODES 50000
#define NEDGES 800000
#define CH_SCAN 512
#define NB_SCAN ((NNODES + CH_SCAN - 1) / CH_SCAN)   // 98

// ---------------- scratch (static device globals; no allocations) ----------
__device__ __half g_z[2 * NNODES * 256];     // fp16 per-etype GEMM output
__device__ float g_h1[NNODES * 128];
__device__ float g_h2[NNODES * 64];
__device__ float g_el[2 * NNODES * 4];
__device__ float g_er[2 * NNODES * 4];
__device__ float g_colsum[256];
__device__ int   g_rp[2][NNODES + 1];
__device__ int   g_cse[2][NEDGES];
__device__ int   g_wp[2][NNODES];
__device__ int   g_bsum[2][128];

// ---------------- f32x2 packed-FMA helpers ----------------
__device__ __forceinline__ unsigned long long bcast2(float v) {
    unsigned long long r;
    asm("mov.b64 %0, {%1, %1};" : "=l"(r) : "f"(v));
    return r;
}
__device__ __forceinline__ void ffma2(unsigned long long& d,
                                      unsigned long long a, unsigned long long b) {
    asm("fma.rn.f32x2 %0, %1, %2, %0;" : "+l"(d) : "l"(a), "l"(b));
}
__device__ __forceinline__ float2 unpack2(unsigned long long v) {
    float2 f;
    asm("mov.b64 {%0, %1}, %2;" : "=f"(f.x), "=f"(f.y) : "l"(v));
    return f;
}

__device__ __forceinline__ float lrelu(float v) {
    return (v > 0.0f) ? v : 0.2f * v;
}
__device__ __forceinline__ float2 h2f(const __half2 h) { return __half22float2(h); }

// ---------------- init: zero CSR counters AND colsum in one launch ----------
__global__ void zero_init(int* __restrict__ rpb, float* __restrict__ csum, int n) {
    int i = blockIdx.x * blockDim.x + threadIdx.x;
    if (i < n) rpb[i] = 0;
    if (i < 256) csum[i] = 0.0f;
}

// ---------------- CSR build pieces ----------------
__global__ void scan_local(int* __restrict__ rpb, int* __restrict__ bsumb) {
    __shared__ int s[CH_SCAN];
    int* rp = rpb + blockIdx.y * (NNODES + 1);
    int* bsum = bsumb + blockIdx.y * 128;
    int tid = threadIdx.x;
    int i = blockIdx.x * CH_SCAN + tid;
    int v = (i < NNODES) ? rp[i] : 0;
    s[tid] = v;
    __syncthreads();
    for (int off = 1; off < CH_SCAN; off <<= 1) {
        int t = (tid >= off) ? s[tid - off] : 0;
        __syncthreads();
        s[tid] += t;
        __syncthreads();
    }
    if (i < NNODES) rp[i] = s[tid] - v;
    if (tid == CH_SCAN - 1) bsum[blockIdx.x] = s[tid];
}

__global__ void scan_add_wp(int* __restrict__ rpb, const int* __restrict__ bsumb,
                            int* __restrict__ wpb) {
    __shared__ int sb[128];
    int tid = threadIdx.x;
    if (tid < 128) {
        int v = (tid < NB_SCAN) ? bsumb[blockIdx.y * 128 + tid] : 0;
        sb[tid] = v;
    }
    __syncthreads();
    for (int off = 1; off < 128; off <<= 1) {
        int t = (tid < 128 && tid >= off) ? sb[tid - off] : 0;
        __syncthreads();
        if (tid < 128) sb[tid] += t;
        __syncthreads();
    }
    int i = blockIdx.x * blockDim.x + tid;
    int* rp = rpb + blockIdx.y * (NNODES + 1);
    int* wp = wpb + blockIdx.y * NNODES;
    if (i < NNODES) {
        int c = i / CH_SCAN;
        int pre = (c == 0) ? 0 : sb[c - 1];
        int v = rp[i] + pre;
        rp[i] = v;
        wp[i] = v;
    }
    if (i == 0) rp[NNODES] = NEDGES;
}

__global__ void fill_k(const int* __restrict__ s0, const int* __restrict__ s1,
                       const int* __restrict__ d0, const int* __restrict__ d1,
                       int* __restrict__ wpb, int* __restrict__ csb) {
    int e = blockIdx.x * blockDim.x + threadIdx.x;
    if (e >= NEDGES) return;
    const int* src = blockIdx.y ? s1 : s0;
    const int* dst = blockIdx.y ? d1 : d0;
    int* wp = wpb + blockIdx.y * NNODES;
    int* cs = csb + blockIdx.y * NEDGES;
    int p = atomicAdd(&wp[dst[e]], 1);
    cs[p] = src[e];
}

// ---------------- GEMM body: double-buffered, f32x2 FMA ----------------
// H==4: z stored head-interleaved (zm[row][lane*8] = {headA quad, headB quad})
template <int K, int HF, int H>
__device__ __forceinline__ void
gemm_body(int bx, int by,
          const float* __restrict__ X, const float* __restrict__ Wb,
          const float* __restrict__ alb, const float* __restrict__ arb,
          __half* __restrict__ Zb, float* __restrict__ elb, float* __restrict__ erb) {
    constexpr int TN = 8, TM = 8, BK = 16;
    constexpr int TX = HF / TN;
    constexpr int TY = 256 / TX;
    constexpr int BM = TM * TY;
    constexpr int BMP = BM + 4;
    constexpr int RW = TX / H;
    constexpr int NT = K / BK;
    constexpr int NX = (BM * BK / 4) / 256;
    constexpr int NW = (BK * HF / 4) / 256;

    __shared__ float xs[2][BK][BMP];
    __shared__ float ws[2][BK][HF];

    const float* W  = Wb  + by * K * HF;
    const float* al = alb + by * HF;
    const float* ar = arb + by * HF;
    __half* Z = Zb  + by * (NNODES * 256);
    float* el = elb + by * (NNODES * 4);
    float* er = erb + by * (NNODES * 4);

    int tid = threadIdx.x;
    int tx = tid % TX;
    int ty = tid / TX;
    int r0 = bx * BM;

    float4 xr[NX], wr[NW];

    auto loadt = [&](int kb) {
#pragma unroll
        for (int it = 0; it < NX; it++) {
            int lin = (tid + it * 256) * 4;
            int r = lin / BK, c = lin % BK;
            int gr = r0 + r;
            xr[it] = (gr < NNODES) ? *(const float4*)&X[gr * K + kb + c]
                                   : make_float4(0.f, 0.f, 0.f, 0.f);
        }
#pragma unroll
        for (int it = 0; it < NW; it++) {
            int lin = (tid + it * 256) * 4;
            int r = lin / HF, c = lin % HF;
            wr[it] = *(const float4*)&W[(kb + r) * HF + c];
        }
    };
    auto storet = [&](int buf) {
#pragma unroll
        for (int it = 0; it < NX; it++) {
            int lin = (tid + it * 256) * 4;
            int r = lin / BK, c = lin % BK;
            xs[buf][c][r] = xr[it].x;
            xs[buf][c + 1][r] = xr[it].y;
            xs[buf][c + 2][r] = xr[it].z;
            xs[buf][c + 3][r] = xr[it].w;
        }
#pragma unroll
        for (int it = 0; it < NW; it++) {
            int lin = (tid + it * 256) * 4;
            int r = lin / HF, c = lin % HF;
            *(float4*)&ws[buf][r][c] = wr[it];
        }
    };

    unsigned long long acc2[TM][TN / 2];
#pragma unroll
    for (int i = 0; i < TM; i++)
#pragma unroll
        for (int j = 0; j < TN / 2; j++) acc2[i][j] = 0ull;

    loadt(0);
    storet(0);
#pragma unroll
    for (int t = 0; t < NT; t++) {
        __syncthreads();
        if (t + 1 < NT) loadt((t + 1) * BK);
        int buf = t & 1;
#pragma unroll
        for (int kk = 0; kk < BK; kk++) {
            float4 a0 = *(const float4*)&xs[buf][kk][ty * 8];
            float4 a1 = *(const float4*)&xs[buf][kk][ty * 8 + 4];
            const unsigned long long* wp64 =
                (const unsigned long long*)&ws[buf][kk][tx * 8];
            unsigned long long bp0 = wp64[0], bp1 = wp64[1],
                               bp2 = wp64[2], bp3 = wp64[3];
            unsigned long long ap[TM] = {
                bcast2(a0.x), bcast2(a0.y), bcast2(a0.z), bcast2(a0.w),
                bcast2(a1.x), bcast2(a1.y), bcast2(a1.z), bcast2(a1.w)};
#pragma unroll
            for (int i = 0; i < TM; i++) {
                ffma2(acc2[i][0], ap[i], bp0);
                ffma2(acc2[i][1], ap[i], bp1);
                ffma2(acc2[i][2], ap[i], bp2);
                ffma2(acc2[i][3], ap[i], bp3);
            }
        }
        if (t + 1 < NT) storet((t + 1) & 1);
    }

    int cbase = tx * TN;
#pragma unroll
    for (int i = 0; i < TM; i++) {
        int row = r0 + ty * TM + i;
        float2 u0 = unpack2(acc2[i][0]);
        float2 u1 = unpack2(acc2[i][1]);
        float2 u2 = unpack2(acc2[i][2]);
        float2 u3 = unpack2(acc2[i][3]);
        float av[TN] = {u0.x, u0.y, u1.x, u1.y, u2.x, u2.y, u3.x, u3.y};
        float pl = 0.0f, pr = 0.0f;
#pragma unroll
        for (int j = 0; j < TN; j++) {
            pl += av[j] * al[cbase + j];
            pr += av[j] * ar[cbase + j];
        }
#pragma unroll
        for (int o = RW / 2; o > 0; o >>= 1) {
            pl += __shfl_xor_sync(0xffffffffu, pl, o);
            pr += __shfl_xor_sync(0xffffffffu, pr, o);
        }
        if (row < NNODES) {
            if constexpr (H == 4) {
                uint2 v0, v1;
                ((__half2*)&v0)[0] = __floats2half2_rn(av[0], av[1]);
                ((__half2*)&v0)[1] = __floats2half2_rn(av[2], av[3]);
                ((__half2*)&v1)[0] = __floats2half2_rn(av[4], av[5]);
                ((__half2*)&v1)[1] = __floats2half2_rn(av[6], av[7]);
                int cm = cbase & 127;
                int hoff = (cbase >= 128) ? 4 : 0;
                int nb0 = (cm >> 2) * 8 + hoff;
                *(uint2*)&Z[row * 256 + nb0] = v0;
                *(uint2*)&Z[row * 256 + nb0 + 8] = v1;
            } else {
                uint4 pack;
                __half2* ph = (__half2*)&pack;
                ph[0] = __floats2half2_rn(av[0], av[1]);
                ph[1] = __floats2half2_rn(av[2], av[3]);
                ph[2] = __floats2half2_rn(av[4], av[5]);
                ph[3] = __floats2half2_rn(av[6], av[7]);
                *(uint4*)&Z[row * HF + cbase] = pack;
            }
            if (tx % RW == 0) {
                int h = tx / RW;
                el[row * H + h] = pl;
                er[row * H + h] = pr;
            }
        }
    }
}

template <int K, int HF, int H>
__global__ void __launch_bounds__(256)
gemm_att(const float* __restrict__ X, const float* __restrict__ Wb,
         const float* __restrict__ alb, const float* __restrict__ arb,
         __half* __restrict__ Zb, float* __restrict__ elb, float* __restrict__ erb) {
    gemm_body<K, HF, H>(blockIdx.x, blockIdx.y, X, Wb, alb, arb, Zb, elb, erb);
}

__global__ void __launch_bounds__(256)
gemm1_count(const float* __restrict__ X, const float* __restrict__ Wb,
            const float* __restrict__ alb, const float* __restrict__ arb,
            __half* __restrict__ Zb, float* __restrict__ elb, float* __restrict__ erb,
            const int* __restrict__ d0, const int* __restrict__ d1,
            int* __restrict__ rpb, int gemmX, int countBlocks) {
    if ((int)blockIdx.x < gemmX) {
        gemm_body<128, 128, 1>(blockIdx.x, blockIdx.y, X, Wb, alb, arb, Zb, elb, erb);
    } else {
        int cb = blockIdx.x - gemmX;
        const int* dst = blockIdx.y ? d1 : d0;
        int* cnt = rpb + blockIdx.y * (NNODES + 1);
        for (int e = cb * 256 + threadIdx.x; e < NEDGES; e += countBlocks * 256)
            atomicAdd(&cnt[dst[e]], 1);
    }
}

// ---------------- single-pass CSR softmax + gather aggregation ----------------
// Edge metadata (cs index, el gather, exp) computed lane-parallel on lanes
// 0..UNR-1, then shuffled to all lanes: removes warp-wide redundant LDG/MUFU.
template <int HF, int H>
__global__ void __launch_bounds__(256)
gat_agg(const int* __restrict__ rp0, const int* __restrict__ cs0,
        const int* __restrict__ rp1, const int* __restrict__ cs1,
        const __half* __restrict__ z0, const __half* __restrict__ z1,
        const float* __restrict__ el0, const float* __restrict__ er0,
        const float* __restrict__ el1, const float* __restrict__ er1,
        const float* __restrict__ bia,
        const float* __restrict__ fc,
        float* __restrict__ out,
        float* __restrict__ colsum) {
    constexpr int VEC = HF / 32;
    __shared__ float scp[256];
    if (HF == 256) {
        scp[threadIdx.x] = 0.0f;
        __syncthreads();
    }
    int w = (blockIdx.x * blockDim.x + threadIdx.x) >> 5;
    int lane = threadIdx.x & 31;

    float c0 = 0.5f, c1 = 0.5f;
    if (fc) { c0 = 0.5f * (fc[0] + fc[2]); c1 = 0.5f * (fc[1] + fc[3]); }

    float acc[VEC];
#pragma unroll
    for (int i = 0; i < VEC; i++) acc[i] = 0.0f;

    if (w < NNODES) {
#pragma unroll
        for (int et = 0; et < 2; et++) {
            const int* rp = et ? rp1 : rp0;
            const int* cs = et ? cs1 : cs0;
            const __half* z = et ? z1 : z0;
            const float* el = et ? el1 : el0;
            const float* er = et ? er1 : er0;
            float ce = et ? c1 : c0;

            int beg = rp[w];
            int end = rp[w + 1];
            if (beg == end) continue;

            float accE[VEC];
#pragma unroll
            for (int i = 0; i < VEC; i++) accE[i] = 0.0f;

            if constexpr (H == 1) {
                constexpr int UNR = (HF == 64) ? 16 : 8;
                float ern = er[w];
                float den = 0.0f;
                int i = beg;
                for (; i + UNR <= end; i += UNR) {
                    // lane-parallel metadata: lanes 0..UNR-1 each handle 1 edge
                    int myS = 0;
                    float myW = 0.0f;
                    if (lane < UNR) {
                        myS = cs[i + lane];
                        myW = __expf(lrelu(el[myS] + ern));
                    }
                    int s[UNR];
                    float wt[UNR];
#pragma unroll
                    for (int u = 0; u < UNR; u++) {
                        s[u] = __shfl_sync(0xffffffffu, myS, u);
                        wt[u] = __shfl_sync(0xffffffffu, myW, u);
                    }
                    if constexpr (HF == 128) {
                        uint2 p[UNR];
#pragma unroll
                        for (int u = 0; u < UNR; u++)
                            p[u] = *(const uint2*)&z[s[u] * 128 + lane * 4];
#pragma unroll
                        for (int u = 0; u < UNR; u++) {
                            float2 f0 = h2f(((const __half2*)&p[u])[0]);
                            float2 f1 = h2f(((const __half2*)&p[u])[1]);
                            accE[0] += wt[u] * f0.x;
                            accE[1] += wt[u] * f0.y;
                            accE[2] += wt[u] * f1.x;
                            accE[3] += wt[u] * f1.y;
                            den += wt[u];
                        }
                    } else {  // HF == 64
                        unsigned p[UNR];
#pragma unroll
                        for (int u = 0; u < UNR; u++)
                            p[u] = *(const unsigned*)&z[s[u] * 64 + lane * 2];
#pragma unroll
                        for (int u = 0; u < UNR; u++) {
                            float2 f0 = h2f(*(const __half2*)&p[u]);
                            accE[0] += wt[u] * f0.x;
                            accE[1] += wt[u] * f0.y;
                            den += wt[u];
                        }
                    }
                }
                for (; i < end; i++) {
                    int s = cs[i];
                    float wt = __expf(lrelu(el[s] + ern));
                    den += wt;
                    if constexpr (HF == 128) {
                        uint2 p = *(const uint2*)&z[s * 128 + lane * 4];
                        float2 f0 = h2f(((const __half2*)&p)[0]);
                        float2 f1 = h2f(((const __half2*)&p)[1]);
                        accE[0] += wt * f0.x; accE[1] += wt * f0.y;
                        accE[2] += wt * f1.x; accE[3] += wt * f1.y;
                    } else {
                        float2 f0 = h2f(*(const __half2*)&z[s * 64 + lane * 2]);
                        accE[0] += wt * f0.x; accE[1] += wt * f0.y;
                    }
                }
                float sc1 = ce / fmaxf(den, 1e-30f);
#pragma unroll
                for (int j = 0; j < VEC; j++) acc[j] += accE[j] * sc1;
            } else {  // H == 4, HF == 256, z head-interleaved
                constexpr int UNR = 4;
                int hsel = lane >> 4;              // 0: heads (0,2); 1: heads (1,3)
                float4 er4 = *(const float4*)&er[w * 4];
                float den0 = 0.0f, den1 = 0.0f;
                int i = beg;
                for (; i + UNR <= end; i += UNR) {
                    // lanes 0..3: each loads 1 edge's cs + all 4 head logits
                    int myS = 0;
                    float4 myW = make_float4(0.f, 0.f, 0.f, 0.f);
                    if (lane < UNR) {
                        myS = cs[i + lane];
                        float4 e4 = *(const float4*)&el[myS * 4];
                        myW.x = __expf(lrelu(e4.x + er4.x));
                        myW.y = __expf(lrelu(e4.y + er4.y));
                        myW.z = __expf(lrelu(e4.z + er4.z));
                        myW.w = __expf(lrelu(e4.w + er4.w));
                    }
                    int s[UNR];
                    float w0[UNR], w1[UNR];
#pragma unroll
                    for (int u = 0; u < UNR; u++) {
                        s[u] = __shfl_sync(0xffffffffu, myS, u);
                        float a = __shfl_sync(0xffffffffu, myW.x, u);  // head 0
                        float b = __shfl_sync(0xffffffffu, myW.y, u);  // head 1
                        float c = __shfl_sync(0xffffffffu, myW.z, u);  // head 2
                        float d = __shfl_sync(0xffffffffu, myW.w, u);  // head 3
                        w0[u] = hsel ? b : a;      // h0 = hsel
                        w1[u] = hsel ? d : c;      // h1 = 2 + hsel
                    }
                    uint4 p[UNR];
#pragma unroll
                    for (int u = 0; u < UNR; u++)
                        p[u] = *(const uint4*)&z[s[u] * 256 + lane * 8];
#pragma unroll
                    for (int u = 0; u < UNR; u++) {
                        float2 f00 = h2f(((const __half2*)&p[u])[0]);
                        float2 f01 = h2f(((const __half2*)&p[u])[1]);
                        float2 f10 = h2f(((const __half2*)&p[u])[2]);
                        float2 f11 = h2f(((const __half2*)&p[u])[3]);
                        accE[0] += w0[u] * f00.x; accE[1] += w0[u] * f00.y;
                        accE[2] += w0[u] * f01.x; accE[3] += w0[u] * f01.y;
                        accE[4] += w1[u] * f10.x; accE[5] += w1[u] * f10.y;
                        accE[6] += w1[u] * f11.x; accE[7] += w1[u] * f11.y;
                        den0 += w0[u];
                        den1 += w1[u];
                    }
                }
                for (; i < end; i++) {
                    int s = cs[i];
                    int h0 = hsel, h1 = 2 + hsel;
                    float ern0 = hsel ? er4.y : er4.x;
                    float ern1 = hsel ? er4.w : er4.z;
                    float w0 = __expf(lrelu(el[s * 4 + h0] + ern0));
                    float w1 = __expf(lrelu(el[s * 4 + h1] + ern1));
                    uint4 p = *(const uint4*)&z[s * 256 + lane * 8];
                    float2 f00 = h2f(((const __half2*)&p)[0]);
                    float2 f01 = h2f(((const __half2*)&p)[1]);
                    float2 f10 = h2f(((const __half2*)&p)[2]);
                    float2 f11 = h2f(((const __half2*)&p)[3]);
                    accE[0] += w0 * f00.x; accE[1] += w0 * f00.y;
                    accE[2] += w0 * f01.x; accE[3] += w0 * f01.y;
                    accE[4] += w1 * f10.x; accE[5] += w1 * f10.y;
                    accE[6] += w1 * f11.x; accE[7] += w1 * f11.y;
                    den0 += w0;
                    den1 += w1;
                }
                float s0 = ce / fmaxf(den0, 1e-30f);
                float s1 = ce / fmaxf(den1, 1e-30f);
#pragma unroll
                for (int j = 0; j < 4; j++) acc[j] += accE[j] * s0;
#pragma unroll
                for (int j = 4; j < 8; j++) acc[j] += accE[j] * s1;
            }
        }

        // write output with combined bias
        if constexpr (HF == 64) {
            int f = lane * 2;
            float2 o;
            o.x = acc[0] + c0 * bia[f] + c1 * bia[64 + f];
            o.y = acc[1] + c0 * bia[f + 1] + c1 * bia[64 + f + 1];
            *(float2*)&out[w * 64 + f] = o;
        } else if constexpr (HF == 128) {
            int f = lane * 4;
            float4 o;
            o.x = acc[0] + c0 * bia[f + 0] + c1 * bia[128 + f + 0];
            o.y = acc[1] + c0 * bia[f + 1] + c1 * bia[128 + f + 1];
            o.z = acc[2] + c0 * bia[f + 2] + c1 * bia[128 + f + 2];
            o.w = acc[3] + c0 * bia[f + 3] + c1 * bia[128 + f + 3];
            *(float4*)&out[w * 128 + f] = o;
        } else {
            int f = lane * 4;
            float4 o0, o1;
            o0.x = acc[0] + 0.5f * (bia[f + 0] + bia[256 + f + 0]);
            o0.y = acc[1] + 0.5f * (bia[f + 1] + bia[256 + f + 1]);
            o0.z = acc[2] + 0.5f * (bia[f + 2] + bia[256 + f + 2]);
            o0.w = acc[3] + 0.5f * (bia[f + 3] + bia[256 + f + 3]);
            o1.x = acc[4] + 0.5f * (bia[128 + f + 0] + bia[256 + 128 + f + 0]);
            o1.y = acc[5] + 0.5f * (bia[128 + f + 1] + bia[256 + 128 + f + 1]);
            o1.z = acc[6] + 0.5f * (bia[128 + f + 2] + bia[256 + 128 + f + 2]);
            o1.w = acc[7] + 0.5f * (bia[128 + f + 3] + bia[256 + 128 + f + 3]);
            *(float4*)&out[w * 256 + f] = o0;
            *(float4*)&out[w * 256 + 128 + f] = o1;
            atomicAdd(&scp[f + 0], o0.x);
            atomicAdd(&scp[f + 1], o0.y);
            atomicAdd(&scp[f + 2], o0.z);
            atomicAdd(&scp[f + 3], o0.w);
            atomicAdd(&scp[128 + f + 0], o1.x);
            atomicAdd(&scp[128 + f + 1], o1.y);
            atomicAdd(&scp[128 + f + 2], o1.z);
            atomicAdd(&scp[128 + f + 3], o1.w);
        }
    }

    if (HF == 256) {
        __syncthreads();
        atomicAdd(&colsum[threadIdx.x], scp[threadIdx.x]);
    }
}

// ---------------- final centering (float4) ----------------
__global__ void center_kernel(float* __restrict__ out, const float* __restrict__ cs) {
    int i = blockIdx.x * blockDim.x + threadIdx.x;     // quad index
    if (i < NNODES * 64) {
        int f = (i & 63) * 4;
        float4 v = *(float4*)&out[i * 4];
        v.x -= cs[f + 0] * (1.0f / NNODES);
        v.y -= cs[f + 1] * (1.0f / NNODES);
        v.z -= cs[f + 2] * (1.0f / NNODES);
        v.w -= cs[f + 3] * (1.0f / NNODES);
        *(float4*)&out[i * 4] = v;
    }
}

// ---------------- orchestration ----------------
extern "C" void kernel_launch(void* const* d_in, const int* in_sizes, int n_in,
                              void* d_out, int out_size) {
    const float* x   = (const float*)d_in[0];
    const int* src0 = (const int*)d_in[1];
    const int* dst0 = (const int*)d_in[2];
    const int* src1 = (const int*)d_in[3];
    const int* dst1 = (const int*)d_in[4];
    const float* W1  = (const float*)d_in[5];
    const float* al1 = (const float*)d_in[6];
    const float* ar1 = (const float*)d_in[7];
    const float* b1  = (const float*)d_in[8];
    const float* W2  = (const float*)d_in[9];
    const float* al2 = (const float*)d_in[10];
    const float* ar2 = (const float*)d_in[11];
    const float* b2  = (const float*)d_in[12];
    const float* Wm  = (const float*)d_in[13];
    const float* alm = (const float*)d_in[14];
    const float* arm = (const float*)d_in[15];
    const float* bm  = (const float*)d_in[16];
    const float* fc  = (const float*)d_in[17];
    float* out = (float*)d_out;

    __half* zb;
    float *h1, *h2, *elb, *erb, *csum;
    int *rpb, *cseb, *wpb, *bsumb;
    cudaGetSymbolAddress((void**)&zb,    g_z);
    cudaGetSymbolAddress((void**)&h1,    g_h1);
    cudaGetSymbolAddress((void**)&h2,    g_h2);
    cudaGetSymbolAddress((void**)&elb,   g_el);
    cudaGetSymbolAddress((void**)&erb,   g_er);
    cudaGetSymbolAddress((void**)&csum,  g_colsum);
    cudaGetSymbolAddress((void**)&rpb,   g_rp);
    cudaGetSymbolAddress((void**)&cseb,  g_cse);
    cudaGetSymbolAddress((void**)&wpb,   g_wp);
    cudaGetSymbolAddress((void**)&bsumb, g_bsum);

    int* rp[2]  = {rpb, rpb + (NNODES + 1)};
    int* cse[2] = {cseb, cseb + NEDGES};
    __half* z[2] = {zb, zb + NNODES * 256};
    float* el[2] = {elb, elb + NNODES * 4};
    float* er[2] = {erb, erb + NNODES * 4};

    const int EG = (NEDGES + 255) / 256;
    const int AGG_BLOCKS = (NNODES * 32 + 255) / 256;

    // ---------------- zero counters + colsum, then fused GEMM1 + count -----
    zero_init<<<(2 * (NNODES + 1) + 255) / 256, 256>>>(rpb, csum, 2 * (NNODES + 1));

    const int GEMM1_X = (NNODES + 127) / 128;
    const int COUNT_B = 256;
    gemm1_count<<<dim3(GEMM1_X + COUNT_B, 2), 256>>>(
        x, W1, al1, ar1, zb, elb, erb, dst0, dst1, rpb, GEMM1_X, COUNT_B);

    // ---------------- finish CSR build ----------------
    scan_local<<<dim3(NB_SCAN, 2), CH_SCAN>>>(rpb, bsumb);
    scan_add_wp<<<dim3((NNODES + 255) / 256, 2), 256>>>(rpb, bsumb, wpb);
    fill_k<<<dim3(EG, 2), 256>>>(src0, src1, dst0, dst1, wpb, cseb);

    // ---------------- layer 1 aggregation ----------------
    gat_agg<128, 1><<<AGG_BLOCKS, 256>>>(
        rp[0], cse[0], rp[1], cse[1], z[0], z[1],
        el[0], er[0], el[1], er[1], b1, nullptr, h1, nullptr);

    // ---------------- layer 2 ----------------
    gemm_att<128, 64, 1><<<dim3((NNODES + 255) / 256, 2), 256>>>(
        h1, W2, al2, ar2, zb, elb, erb);
    gat_agg<64, 1><<<AGG_BLOCKS, 256>>>(
        rp[0], cse[0], rp[1], cse[1], z[0], z[1],
        el[0], er[0], el[1], er[1], b2, fc, h2, nullptr);

    // ---------------- layer MH ----------------
    gemm_att<64, 256, 4><<<dim3((NNODES + 63) / 64, 2), 256>>>(
        h2, Wm, alm, arm, zb, elb, erb);
    gat_agg<256, 4><<<AGG_BLOCKS, 256>>>(
        rp[0], cse[0], rp[1], cse[1], z[0], z[1],
        el[0], er[0], el[1], er[1], bm, nullptr, out, csum);

    // ---------------- final per-column mean centering -------------------
    center_kernel<<<(NNODES * 64 + 255) / 256, 256>>>(out, csum);
}